// round 1
// baseline (speedup 1.0000x reference)
#include <cuda_runtime.h>
#include <cstdint>

// Problem constants
#define BB   4
#define TT   1024
#define EE   512
#define SSQ  1536   // S = T + E
#define HHC  1024   // hidden
#define NHH  16
#define HDD  64
#define LN_EPS 1e-5f
#define SCALING 0.125f   // sqrt(64)/64

// ---------------- scratch (__device__ globals; no allocation allowed) ----------------
__device__ float g_Q  [BB*TT*HHC];    // rope'd Q, [B,T,H]
__device__ float g_K  [BB*TT*HHC];    // raw K projection
__device__ float g_V  [BB*TT*HHC];    // raw V projection
__device__ float g_Kex[BB*SSQ*HHC];   // gathered + rope'd K, [B,S,H]
__device__ float g_Vex[BB*SSQ*HHC];   // gathered V, [B,S,H]
__device__ float g_att[BB*TT*HHC];    // attention out pre-LN, [B,T,H]
__device__ float g_ln [BB*TT*HHC];    // LN output

// ---------------- helpers ----------------
__device__ __forceinline__ uint32_t f2tf(float f) {
    uint32_t u; asm("cvt.rna.tf32.f32 %0, %1;" : "=r"(u) : "f"(f)); return u;
}

// ---------------- GEMM: C[M,N] = alpha * A[M,K] * B[N,K]^T (tf32 mma.sync) ----------------
__global__ __launch_bounds__(256) void gemm_tf32_nt(
    const float* __restrict__ A, const float* __restrict__ Bm,
    float* __restrict__ C, int M, int N, int K, float alpha)
{
    __shared__ uint32_t As[128 * 36];
    __shared__ uint32_t Bs[128 * 36];

    const int tid  = threadIdx.x;
    const int lane = tid & 31;
    const int wid  = tid >> 5;
    const int gid  = lane >> 2;    // group id (row within 8)
    const int tig  = lane & 3;     // thread in group (k / col quarter)
    const int wm   = (wid & 1) * 64;
    const int wn   = (wid >> 1) * 32;
    const int bm   = blockIdx.y * 128;
    const int bn   = blockIdx.x * 128;

    float acc[4][4][4];
#pragma unroll
    for (int i = 0; i < 4; i++)
#pragma unroll
        for (int j = 0; j < 4; j++)
#pragma unroll
            for (int r = 0; r < 4; r++) acc[i][j][r] = 0.f;

    for (int kt = 0; kt < K; kt += 32) {
#pragma unroll
        for (int it = 0; it < 4; it++) {
            int f4 = tid + it * 256;       // 0..1023 float4 slots
            int r  = f4 >> 3;              // 0..127
            int c  = (f4 & 7) << 2;        // 0,4,...,28
            float4 a = *reinterpret_cast<const float4*>(A + (size_t)(bm + r) * K + kt + c);
            uint32_t* d = &As[r * 36 + c];
            d[0] = f2tf(a.x); d[1] = f2tf(a.y); d[2] = f2tf(a.z); d[3] = f2tf(a.w);
            float4 b = *reinterpret_cast<const float4*>(Bm + (size_t)(bn + r) * K + kt + c);
            uint32_t* e = &Bs[r * 36 + c];
            e[0] = f2tf(b.x); e[1] = f2tf(b.y); e[2] = f2tf(b.z); e[3] = f2tf(b.w);
        }
        __syncthreads();
#pragma unroll
        for (int ks = 0; ks < 32; ks += 8) {
            uint32_t af[4][4], bf[4][2];
#pragma unroll
            for (int mt = 0; mt < 4; mt++) {
                const uint32_t* p = &As[(wm + mt * 16 + gid) * 36 + ks + tig];
                af[mt][0] = p[0];
                af[mt][1] = p[8 * 36];
                af[mt][2] = p[4];
                af[mt][3] = p[8 * 36 + 4];
            }
#pragma unroll
            for (int nt = 0; nt < 4; nt++) {
                const uint32_t* p = &Bs[(wn + nt * 8 + gid) * 36 + ks + tig];
                bf[nt][0] = p[0];
                bf[nt][1] = p[4];
            }
#pragma unroll
            for (int mt = 0; mt < 4; mt++)
#pragma unroll
                for (int nt = 0; nt < 4; nt++)
                    asm volatile(
                        "mma.sync.aligned.m16n8k8.row.col.f32.tf32.tf32.f32 "
                        "{%0,%1,%2,%3},{%4,%5,%6,%7},{%8,%9},{%0,%1,%2,%3};"
                        : "+f"(acc[mt][nt][0]), "+f"(acc[mt][nt][1]),
                          "+f"(acc[mt][nt][2]), "+f"(acc[mt][nt][3])
                        : "r"(af[mt][0]), "r"(af[mt][1]), "r"(af[mt][2]), "r"(af[mt][3]),
                          "r"(bf[nt][0]), "r"(bf[nt][1]));
        }
        __syncthreads();
    }

#pragma unroll
    for (int mt = 0; mt < 4; mt++) {
#pragma unroll
        for (int nt = 0; nt < 4; nt++) {
            int r0 = bm + wm + mt * 16 + gid;
            int c0 = bn + wn + nt * 8 + tig * 2;
            float2 v01 = make_float2(acc[mt][nt][0] * alpha, acc[mt][nt][1] * alpha);
            float2 v23 = make_float2(acc[mt][nt][2] * alpha, acc[mt][nt][3] * alpha);
            *reinterpret_cast<float2*>(C + (size_t)r0 * N + c0)       = v01;
            *reinterpret_cast<float2*>(C + (size_t)(r0 + 8) * N + c0) = v23;
        }
    }
}

// ---------------- RoPE on Q (in place), position = t ----------------
__global__ __launch_bounds__(256) void rope_q_kernel()
{
    int idx = blockIdx.x * blockDim.x + threadIdx.x;   // BB*TT*NHH*32 total
    int i    = idx & 31;
    int head = (idx >> 5) & (NHH - 1);
    int row  = idx >> 9;            // b*TT + t
    int t    = row & (TT - 1);
    float* p = g_Q + (size_t)row * HHC + head * HDD + i;
    float x1 = p[0], x2 = p[32];
    double invf = exp(-0.28782313662425573 * (double)i);   // ln(10000)/32
    float arg = (float)t * (float)invf;
    float s, c; sincosf(arg, &s, &c);
    p[0]  = x1 * c - x2 * s;
    p[32] = x2 * c + x1 * s;
}

// ---------------- Gather K/V (PBC expansion) + RoPE on K (position = s) ----------------
__global__ __launch_bounds__(256) void gather_kv_kernel(const int* __restrict__ outcell)
{
    int idx = blockIdx.x * blockDim.x + threadIdx.x;   // BB*SSQ*NHH*32 total
    int i    = idx & 31;
    int head = (idx >> 5) & (NHH - 1);
    int rest = idx >> 9;
    int s    = rest % SSQ;
    int b    = rest / SSQ;
    int src  = (s < TT) ? s : outcell[b * EE + (s - TT)];

    size_t soff = (size_t)(b * TT + src) * HHC + head * HDD + i;
    size_t doff = (size_t)(b * SSQ + s) * HHC + head * HDD + i;

    float k1 = g_K[soff], k2 = g_K[soff + 32];
    double invf = exp(-0.28782313662425573 * (double)i);
    float arg = (float)s * (float)invf;
    float sn, cs; sincosf(arg, &sn, &cs);
    g_Kex[doff]      = k1 * cs - k2 * sn;
    g_Kex[doff + 32] = k2 * cs + k1 * sn;

    g_Vex[doff]      = g_V[soff];
    g_Vex[doff + 32] = g_V[soff + 32];
}

// ---------------- Attention: flash-style, fp32 SIMT ----------------
// grid (T/64, NH, B), 256 threads (8 warps). Warp w owns q rows w*8..w*8+7.
// Each lane owns k columns {lane, lane+32} (scores) and dims {lane, lane+32} (PV).
__global__ __launch_bounds__(256) void attn_kernel(
    const float* __restrict__ bias, const float* __restrict__ lw,
    const unsigned char* __restrict__ keypad, const unsigned char* __restrict__ expand)
{
    extern __shared__ float sm[];
    float* qs    = sm;                 // 64 x 65
    float* ks    = qs + 64 * 65;       // 64 x 65
    float* vs    = ks + 64 * 65;       // 64 x 65
    float* ps    = vs + 64 * 65;       // 64 x 64 (p * lw per q row)
    float* maskf = ps + 64 * 64;       // 64

    const int tid  = threadIdx.x;
    const int lane = tid & 31;
    const int w    = tid >> 5;
    const int qt   = blockIdx.x, h = blockIdx.y, b = blockIdx.z;
    const int q0   = qt * 64;

    for (int i = tid; i < 64 * 64; i += 256) {
        int r = i >> 6, d = i & 63;
        qs[r * 65 + d] = g_Q[(size_t)(b * TT + q0 + r) * HHC + h * HDD + d];
    }

    float m[8], l[8], acc0[8], acc1[8];
#pragma unroll
    for (int q = 0; q < 8; q++) { m[q] = -INFINITY; l[q] = 0.f; acc0[q] = 0.f; acc1[q] = 0.f; }

    const float* biasB = bias + (size_t)(b * NHH + h) * TT * SSQ;
    const float* lwB   = lw + (size_t)b * TT * SSQ;

    for (int kc = 0; kc < SSQ; kc += 64) {
        __syncthreads();
        for (int i = tid; i < 64 * 64; i += 256) {
            int r = i >> 6, d = i & 63;
            size_t off = (size_t)(b * SSQ + kc + r) * HHC + h * HDD + d;
            ks[r * 65 + d] = g_Kex[off];
            vs[r * 65 + d] = g_Vex[off];
        }
        if (tid < 64) {
            int s = kc + tid;
            unsigned char mk = (s < TT) ? keypad[b * TT + s] : expand[b * EE + (s - TT)];
            maskf[tid] = mk ? 1.f : 0.f;
        }
        __syncthreads();

        // ---- scores: d-outer, q-inner register blocking ----
        float s0[8], s1[8];
#pragma unroll
        for (int q = 0; q < 8; q++) { s0[q] = 0.f; s1[q] = 0.f; }
        {
            const float* k0p = ks + lane * 65;
            const float* k1p = ks + (lane + 32) * 65;
            const float* qbase = qs + (w * 8) * 65;
#pragma unroll
            for (int d = 0; d < 64; d++) {
                float k0v = k0p[d], k1v = k1p[d];
#pragma unroll
                for (int q = 0; q < 8; q++) {
                    float qv = qbase[q * 65 + d];
                    s0[q] = fmaf(qv, k0v, s0[q]);
                    s1[q] = fmaf(qv, k1v, s1[q]);
                }
            }
        }

        // ---- bias, masks, online softmax, p*lw into smem ----
        float mk0 = maskf[lane], mk1 = maskf[lane + 32];
#pragma unroll
        for (int qr = 0; qr < 8; qr++) {
            int q = w * 8 + qr;
            size_t rowoff = (size_t)(q0 + q) * SSQ + kc;
            float b0 = biasB[rowoff + lane];
            float b1 = biasB[rowoff + lane + 32];
            float lw0 = lwB[rowoff + lane];
            float lw1 = lwB[rowoff + lane + 32];
            float v0 = s0[qr] + b0;
            float v1 = s1[qr] + b1;
            v0 = (mk0 != 0.f || lw0 <= 1e-5f) ? -INFINITY : v0;
            v1 = (mk1 != 0.f || lw1 <= 1e-5f) ? -INFINITY : v1;

            float cm = fmaxf(v0, v1);
#pragma unroll
            for (int o = 16; o; o >>= 1) cm = fmaxf(cm, __shfl_xor_sync(0xffffffffu, cm, o));
            float mn = fmaxf(m[qr], cm);
            float scale, p0, p1;
            if (mn == -INFINITY) { scale = 1.f; p0 = 0.f; p1 = 0.f; }
            else {
                scale = expf(m[qr] - mn);
                p0 = expf(v0 - mn);
                p1 = expf(v1 - mn);
            }
            m[qr] = mn;
            float psum = p0 + p1;
#pragma unroll
            for (int o = 16; o; o >>= 1) psum += __shfl_xor_sync(0xffffffffu, psum, o);
            l[qr]    = l[qr] * scale + psum;
            acc0[qr] *= scale;
            acc1[qr] *= scale;
            ps[q * 64 + lane]      = p0 * lw0;
            ps[q * 64 + lane + 32] = p1 * lw1;
        }
        __syncwarp();

        // ---- PV: k-outer, q-inner ----
        {
            float a0[8], a1[8];
#pragma unroll
            for (int q = 0; q < 8; q++) { a0[q] = 0.f; a1[q] = 0.f; }
            const float* pbase = ps + (w * 8) * 64;
#pragma unroll
            for (int k2 = 0; k2 < 64; k2++) {
                float v0v = vs[k2 * 65 + lane];
                float v1v = vs[k2 * 65 + lane + 32];
#pragma unroll
                for (int q = 0; q < 8; q++) {
                    float pk = pbase[q * 64 + k2];
                    a0[q] = fmaf(pk, v0v, a0[q]);
                    a1[q] = fmaf(pk, v1v, a1[q]);
                }
            }
#pragma unroll
            for (int q = 0; q < 8; q++) { acc0[q] += a0[q]; acc1[q] += a1[q]; }
        }
    }

#pragma unroll
    for (int qr = 0; qr < 8; qr++) {
        int q = w * 8 + qr;
        float inv = 1.f / l[qr];
        size_t o = (size_t)(b * TT + q0 + q) * HHC + h * HDD;
        g_att[o + lane]      = acc0[qr] * inv;
        g_att[o + lane + 32] = acc1[qr] * inv;
    }
}

// ---------------- LayerNorm over H=1024 ----------------
__global__ __launch_bounds__(256) void ln_kernel(
    const float* __restrict__ gam, const float* __restrict__ bet)
{
    __shared__ float red[2][32];
    int row = blockIdx.x;
    const float* x = g_att + (size_t)row * HHC;
    float v[4], s = 0.f, sq = 0.f;
#pragma unroll
    for (int i = 0; i < 4; i++) {
        v[i] = x[threadIdx.x + i * 256];
        s += v[i]; sq += v[i] * v[i];
    }
#pragma unroll
    for (int o = 16; o; o >>= 1) {
        s  += __shfl_xor_sync(0xffffffffu, s,  o);
        sq += __shfl_xor_sync(0xffffffffu, sq, o);
    }
    int lane = threadIdx.x & 31, w = threadIdx.x >> 5;
    if (lane == 0) { red[0][w] = s; red[1][w] = sq; }
    __syncthreads();
    if (w == 0) {
        s  = (lane < 8) ? red[0][lane] : 0.f;
        sq = (lane < 8) ? red[1][lane] : 0.f;
#pragma unroll
        for (int o = 4; o; o >>= 1) {
            s  += __shfl_xor_sync(0xffffffffu, s,  o);
            sq += __shfl_xor_sync(0xffffffffu, sq, o);
        }
        if (lane == 0) { red[0][0] = s; red[1][0] = sq; }
    }
    __syncthreads();
    float mu  = red[0][0] * (1.f / HHC);
    float var = red[1][0] * (1.f / HHC) - mu * mu;
    float rs  = rsqrtf(var + LN_EPS);
#pragma unroll
    for (int i = 0; i < 4; i++) {
        int c = threadIdx.x + i * 256;
        g_ln[(size_t)row * HHC + c] = (v[i] - mu) * rs * gam[c] + bet[c];
    }
}

// ---------------- launch ----------------
extern "C" void kernel_launch(void* const* d_in, const int* in_sizes, int n_in,
                              void* d_out, int out_size)
{
    const float* x    = (const float*)d_in[0];
    const float* bias = (const float*)d_in[1];
    const float* lw   = (const float*)d_in[2];
    const unsigned char* kpm = (const unsigned char*)d_in[3];
    const int*   outcell = (const int*)d_in[4];
    const unsigned char* epm = (const unsigned char*)d_in[5];
    const float* wq  = (const float*)d_in[6];
    const float* wk  = (const float*)d_in[7];
    const float* wv  = (const float*)d_in[8];
    const float* wo  = (const float*)d_in[9];
    const float* lng = (const float*)d_in[10];
    const float* lnb = (const float*)d_in[11];
    float* out = (float*)d_out;

    float *Q, *K, *V, *LN;
    cudaGetSymbolAddress((void**)&Q,  g_Q);
    cudaGetSymbolAddress((void**)&K,  g_K);
    cudaGetSymbolAddress((void**)&V,  g_V);
    cudaGetSymbolAddress((void**)&LN, g_ln);

    dim3 gg(HHC / 128, (BB * TT) / 128);   // (8, 32)
    gemm_tf32_nt<<<gg, 256>>>(x, wq, Q, BB * TT, HHC, HHC, SCALING);
    gemm_tf32_nt<<<gg, 256>>>(x, wk, K, BB * TT, HHC, HHC, 1.f);
    gemm_tf32_nt<<<gg, 256>>>(x, wv, V, BB * TT, HHC, HHC, 1.f);

    rope_q_kernel<<<(BB * TT * NHH * 32) / 256, 256>>>();
    gather_kv_kernel<<<(BB * SSQ * NHH * 32) / 256, 256>>>(outcell);

    int smem = (3 * 64 * 65 + 64 * 64 + 64) * (int)sizeof(float);  // 66560 B
    cudaFuncSetAttribute(attn_kernel, cudaFuncAttributeMaxDynamicSharedMemorySize, smem);
    attn_kernel<<<dim3(TT / 64, NHH, BB), 256, smem>>>(bias, lw, kpm, epm);

    ln_kernel<<<BB * TT, 256>>>(lng, lnb);

    gemm_tf32_nt<<<gg, 256>>>(LN, wo, out, BB * TT, HHC, HHC, 1.f);
}

// round 3
// speedup vs baseline: 1.9125x; 1.9125x over previous
#include <cuda_runtime.h>
#include <cuda_bf16.h>
#include <cstdint>

// Problem constants
#define BB   4
#define TT   1024
#define EE   512
#define SSQ  1536   // S = T + E
#define HHC  1024   // hidden
#define NHH  16
#define HDD  64
#define LN_EPS 1e-5f
#define SCALING 0.125f   // sqrt(64)/64

// -log2(10000)/32
#define NLOG2F_STEP (-0.4152410118609203f)

// ---------------- scratch ----------------
__device__ float g_Q  [BB*TT*HHC];    // rope'd Q, [B,T,H]
__device__ float g_K  [BB*TT*HHC];    // raw K projection
__device__ float g_V  [BB*TT*HHC];    // raw V projection
__device__ float g_Kex[BB*SSQ*HHC];   // gathered + rope'd K, [B,S,H]
__device__ float g_Vex[BB*SSQ*HHC];   // gathered V, [B,S,H]
__device__ float g_att[BB*TT*HHC];    // attention out pre-LN
__device__ float g_ln [BB*TT*HHC];    // LN output

// ---------------- helpers ----------------
__device__ __forceinline__ uint32_t f2tf(float f) {
    uint32_t u; asm("cvt.rna.tf32.f32 %0, %1;" : "=r"(u) : "f"(f)); return u;
}

__device__ __forceinline__ void bsplit(float x, __nv_bfloat16& h, __nv_bfloat16& l) {
    h = __float2bfloat16_rn(x);
    l = __float2bfloat16_rn(x - __bfloat162float(h));
}

__device__ __forceinline__ void mma16816(float* c,
    uint32_t a0, uint32_t a1, uint32_t a2, uint32_t a3,
    uint32_t b0, uint32_t b1)
{
    asm volatile(
        "mma.sync.aligned.m16n8k16.row.col.f32.bf16.bf16.f32 "
        "{%0,%1,%2,%3},{%4,%5,%6,%7},{%8,%9},{%0,%1,%2,%3};"
        : "+f"(c[0]), "+f"(c[1]), "+f"(c[2]), "+f"(c[3])
        : "r"(a0), "r"(a1), "r"(a2), "r"(a3), "r"(b0), "r"(b1));
}

// ---------------- GEMM: C[M,N] = alpha * A[M,K] * B[N,K]^T (tf32 mma.sync) ----------------
__global__ __launch_bounds__(256) void gemm_tf32_nt(
    const float* __restrict__ A, const float* __restrict__ Bm,
    float* __restrict__ C, int M, int N, int K, float alpha)
{
    __shared__ uint32_t As[128 * 36];
    __shared__ uint32_t Bs[128 * 36];

    const int tid  = threadIdx.x;
    const int lane = tid & 31;
    const int wid  = tid >> 5;
    const int gid  = lane >> 2;
    const int tig  = lane & 3;
    const int wm   = (wid & 1) * 64;
    const int wn   = (wid >> 1) * 32;
    const int bm   = blockIdx.y * 128;
    const int bn   = blockIdx.x * 128;

    float acc[4][4][4];
#pragma unroll
    for (int i = 0; i < 4; i++)
#pragma unroll
        for (int j = 0; j < 4; j++)
#pragma unroll
            for (int r = 0; r < 4; r++) acc[i][j][r] = 0.f;

    for (int kt = 0; kt < K; kt += 32) {
#pragma unroll
        for (int it = 0; it < 4; it++) {
            int f4 = tid + it * 256;
            int r  = f4 >> 3;
            int c  = (f4 & 7) << 2;
            float4 a = *reinterpret_cast<const float4*>(A + (size_t)(bm + r) * K + kt + c);
            uint32_t* d = &As[r * 36 + c];
            d[0] = f2tf(a.x); d[1] = f2tf(a.y); d[2] = f2tf(a.z); d[3] = f2tf(a.w);
            float4 b = *reinterpret_cast<const float4*>(Bm + (size_t)(bn + r) * K + kt + c);
            uint32_t* e = &Bs[r * 36 + c];
            e[0] = f2tf(b.x); e[1] = f2tf(b.y); e[2] = f2tf(b.z); e[3] = f2tf(b.w);
        }
        __syncthreads();
#pragma unroll
        for (int ks = 0; ks < 32; ks += 8) {
            uint32_t af[4][4], bf[4][2];
#pragma unroll
            for (int mt = 0; mt < 4; mt++) {
                const uint32_t* p = &As[(wm + mt * 16 + gid) * 36 + ks + tig];
                af[mt][0] = p[0];
                af[mt][1] = p[8 * 36];
                af[mt][2] = p[4];
                af[mt][3] = p[8 * 36 + 4];
            }
#pragma unroll
            for (int nt = 0; nt < 4; nt++) {
                const uint32_t* p = &Bs[(wn + nt * 8 + gid) * 36 + ks + tig];
                bf[nt][0] = p[0];
                bf[nt][1] = p[4];
            }
#pragma unroll
            for (int mt = 0; mt < 4; mt++)
#pragma unroll
                for (int nt = 0; nt < 4; nt++)
                    asm volatile(
                        "mma.sync.aligned.m16n8k8.row.col.f32.tf32.tf32.f32 "
                        "{%0,%1,%2,%3},{%4,%5,%6,%7},{%8,%9},{%0,%1,%2,%3};"
                        : "+f"(acc[mt][nt][0]), "+f"(acc[mt][nt][1]),
                          "+f"(acc[mt][nt][2]), "+f"(acc[mt][nt][3])
                        : "r"(af[mt][0]), "r"(af[mt][1]), "r"(af[mt][2]), "r"(af[mt][3]),
                          "r"(bf[nt][0]), "r"(bf[nt][1]));
        }
        __syncthreads();
    }

#pragma unroll
    for (int mt = 0; mt < 4; mt++) {
#pragma unroll
        for (int nt = 0; nt < 4; nt++) {
            int r0 = bm + wm + mt * 16 + gid;
            int c0 = bn + wn + nt * 8 + tig * 2;
            float2 v01 = make_float2(acc[mt][nt][0] * alpha, acc[mt][nt][1] * alpha);
            float2 v23 = make_float2(acc[mt][nt][2] * alpha, acc[mt][nt][3] * alpha);
            *reinterpret_cast<float2*>(C + (size_t)r0 * N + c0)       = v01;
            *reinterpret_cast<float2*>(C + (size_t)(r0 + 8) * N + c0) = v23;
        }
    }
}

// ---------------- RoPE on Q (in place), fp32 math ----------------
__global__ __launch_bounds__(256) void rope_q_kernel()
{
    int idx = blockIdx.x * blockDim.x + threadIdx.x;
    int i    = idx & 31;
    int head = (idx >> 5) & (NHH - 1);
    int row  = idx >> 9;
    int t    = row & (TT - 1);
    float* p = g_Q + (size_t)row * HHC + head * HDD + i;
    float x1 = p[0], x2 = p[32];
    float invf = exp2f(NLOG2F_STEP * (float)i);
    float arg = (float)t * invf;
    float s, c; sincosf(arg, &s, &c);
    p[0]  = x1 * c - x2 * s;
    p[32] = x2 * c + x1 * s;
}

// ---------------- Gather K/V + RoPE on K, fp32 math ----------------
__global__ __launch_bounds__(256) void gather_kv_kernel(const int* __restrict__ outcell)
{
    int idx = blockIdx.x * blockDim.x + threadIdx.x;
    int i    = idx & 31;
    int head = (idx >> 5) & (NHH - 1);
    int rest = idx >> 9;
    int s    = rest % SSQ;
    int b    = rest / SSQ;
    int src  = (s < TT) ? s : outcell[b * EE + (s - TT)];

    size_t soff = (size_t)(b * TT + src) * HHC + head * HDD + i;
    size_t doff = (size_t)(b * SSQ + s) * HHC + head * HDD + i;

    float k1 = g_K[soff], k2 = g_K[soff + 32];
    float invf = exp2f(NLOG2F_STEP * (float)i);
    float arg = (float)s * invf;
    float sn, cs; sincosf(arg, &sn, &cs);
    g_Kex[doff]      = k1 * cs - k2 * sn;
    g_Kex[doff + 32] = k2 * cs + k1 * sn;

    g_Vex[doff]      = g_V[soff];
    g_Vex[doff + 32] = g_V[soff + 32];
}

// ---------------- Attention: flash, bf16x2-split mma tensor cores ----------------
// grid (T/128, NH, B), 256 threads. Warp w owns q rows [w*16, w*16+16).
// K tile = 64 keys. Frag conventions (mma.m16n8k16): gid=lane>>2, tig=lane&3.
#define ATT_SMEM 37120
__global__ __launch_bounds__(256) void attn_mma_kernel(
    const float* __restrict__ bias, const float* __restrict__ lw,
    const unsigned char* __restrict__ keypad, const unsigned char* __restrict__ expand)
{
    extern __shared__ char smraw[];
    __nv_bfloat16* Qhi  = (__nv_bfloat16*)smraw;        // [128][72]
    __nv_bfloat16* Qlo  = Qhi + 128 * 72;
    __nv_bfloat16* Khi  = (__nv_bfloat16*)smraw;        // [64][72] (key-major)
    __nv_bfloat16* Klo  = Khi + 64 * 72;
    __nv_bfloat16* Vthi = Klo + 64 * 72;                // [64][72] (d-major, transposed)
    __nv_bfloat16* Vtlo = Vthi + 64 * 72;
    float* maskS = (float*)(smraw + 4 * 64 * 72 * 2);   // 64 floats

    const int tid  = threadIdx.x;
    const int lane = tid & 31;
    const int w    = tid >> 5;
    const int gid  = lane >> 2;
    const int tig  = lane & 3;
    const int h = blockIdx.y, b = blockIdx.z;
    const int q0 = blockIdx.x * 128;
    const int qw = w * 16;

    // ---- stage Q (split to bf16 hi/lo) ----
#pragma unroll
    for (int it = 0; it < 8; it++) {
        int f4 = tid + it * 256;           // 0..2047
        int r  = f4 >> 4;                  // 0..127
        int c  = (f4 & 15) * 4;
        float4 v = *(const float4*)(g_Q + (size_t)(b * TT + q0 + r) * HHC + h * HDD + c);
        __nv_bfloat16 hh, ll;
        bsplit(v.x, hh, ll); Qhi[r*72+c+0] = hh; Qlo[r*72+c+0] = ll;
        bsplit(v.y, hh, ll); Qhi[r*72+c+1] = hh; Qlo[r*72+c+1] = ll;
        bsplit(v.z, hh, ll); Qhi[r*72+c+2] = hh; Qlo[r*72+c+2] = ll;
        bsplit(v.w, hh, ll); Qhi[r*72+c+3] = hh; Qlo[r*72+c+3] = ll;
    }
    __syncthreads();

    // ---- Q fragments (resident for whole CTA) ----
    uint32_t qh[4][4], ql[4][4];
#pragma unroll
    for (int ks = 0; ks < 4; ks++) {
        int c0 = 2 * tig + 16 * ks;
        qh[ks][0] = *(uint32_t*)&Qhi[(qw + gid)     * 72 + c0];
        qh[ks][1] = *(uint32_t*)&Qhi[(qw + gid + 8) * 72 + c0];
        qh[ks][2] = *(uint32_t*)&Qhi[(qw + gid)     * 72 + c0 + 8];
        qh[ks][3] = *(uint32_t*)&Qhi[(qw + gid + 8) * 72 + c0 + 8];
        ql[ks][0] = *(uint32_t*)&Qlo[(qw + gid)     * 72 + c0];
        ql[ks][1] = *(uint32_t*)&Qlo[(qw + gid + 8) * 72 + c0];
        ql[ks][2] = *(uint32_t*)&Qlo[(qw + gid)     * 72 + c0 + 8];
        ql[ks][3] = *(uint32_t*)&Qlo[(qw + gid + 8) * 72 + c0 + 8];
    }

    float m0 = -INFINITY, m1 = -INFINITY, l0 = 0.f, l1 = 0.f;
    float pacc[8][4];
#pragma unroll
    for (int nt = 0; nt < 8; nt++)
#pragma unroll
        for (int c = 0; c < 4; c++) pacc[nt][c] = 0.f;

    const float* biasB = bias + ((size_t)(b * NHH + h) * TT + q0) * SSQ;
    const float* lwB   = lw   + ((size_t)b * TT + q0) * SSQ;

    for (int kc = 0; kc < SSQ; kc += 64) {
        __syncthreads();
        // ---- load K/V tile (split; V transposed) ----
#pragma unroll
        for (int it = 0; it < 4; it++) {
            int f4 = tid + it * 256;       // 0..1023
            int r  = f4 >> 4;              // key 0..63
            int c  = (f4 & 15) * 4;        // d
            size_t off = (size_t)(b * SSQ + kc + r) * HHC + h * HDD + c;
            float4 kv = *(const float4*)(g_Kex + off);
            __nv_bfloat16 hh, ll;
            bsplit(kv.x, hh, ll); Khi[r*72+c+0] = hh; Klo[r*72+c+0] = ll;
            bsplit(kv.y, hh, ll); Khi[r*72+c+1] = hh; Klo[r*72+c+1] = ll;
            bsplit(kv.z, hh, ll); Khi[r*72+c+2] = hh; Klo[r*72+c+2] = ll;
            bsplit(kv.w, hh, ll); Khi[r*72+c+3] = hh; Klo[r*72+c+3] = ll;
            float4 vv = *(const float4*)(g_Vex + off);
            bsplit(vv.x, hh, ll); Vthi[(c+0)*72+r] = hh; Vtlo[(c+0)*72+r] = ll;
            bsplit(vv.y, hh, ll); Vthi[(c+1)*72+r] = hh; Vtlo[(c+1)*72+r] = ll;
            bsplit(vv.z, hh, ll); Vthi[(c+2)*72+r] = hh; Vtlo[(c+2)*72+r] = ll;
            bsplit(vv.w, hh, ll); Vthi[(c+3)*72+r] = hh; Vtlo[(c+3)*72+r] = ll;
        }
        if (tid < 64) {
            int s = kc + tid;
            unsigned char mk = (s < TT) ? keypad[b * TT + s] : expand[b * EE + (s - TT)];
            maskS[tid] = mk ? 1.f : 0.f;
        }
        __syncthreads();

        // ---- QK^T (3-pass bf16x2) ----
        float sacc[8][4];
#pragma unroll
        for (int nt = 0; nt < 8; nt++)
#pragma unroll
            for (int c = 0; c < 4; c++) sacc[nt][c] = 0.f;

#pragma unroll
        for (int ks = 0; ks < 4; ks++) {
#pragma unroll
            for (int nt = 0; nt < 8; nt++) {
                int rr = (8 * nt + gid) * 72 + 2 * tig + 16 * ks;
                uint32_t bh0 = *(uint32_t*)&Khi[rr];
                uint32_t bh1 = *(uint32_t*)&Khi[rr + 8];
                uint32_t bl0 = *(uint32_t*)&Klo[rr];
                uint32_t bl1 = *(uint32_t*)&Klo[rr + 8];
                mma16816(sacc[nt], qh[ks][0], qh[ks][1], qh[ks][2], qh[ks][3], bh0, bh1);
                mma16816(sacc[nt], ql[ks][0], ql[ks][1], ql[ks][2], ql[ks][3], bh0, bh1);
                mma16816(sacc[nt], qh[ks][0], qh[ks][1], qh[ks][2], qh[ks][3], bl0, bl1);
            }
        }

        // ---- pass 1: + bias, masks, row max ----
        float rmax0 = -INFINITY, rmax1 = -INFINITY;
#pragma unroll
        for (int nt = 0; nt < 8; nt++) {
            int col = kc + 8 * nt + 2 * tig;
            float2 bb0 = __ldg((const float2*)(biasB + (size_t)(qw + gid)     * SSQ + col));
            float2 bb1 = __ldg((const float2*)(biasB + (size_t)(qw + gid + 8) * SSQ + col));
            float2 w0  = __ldg((const float2*)(lwB   + (size_t)(qw + gid)     * SSQ + col));
            float2 w1  = __ldg((const float2*)(lwB   + (size_t)(qw + gid + 8) * SSQ + col));
            float mk0 = maskS[8 * nt + 2 * tig];
            float mk1 = maskS[8 * nt + 2 * tig + 1];
            float v0 = sacc[nt][0] + bb0.x; if (mk0 != 0.f || w0.x <= 1e-5f) v0 = -INFINITY;
            float v1 = sacc[nt][1] + bb0.y; if (mk1 != 0.f || w0.y <= 1e-5f) v1 = -INFINITY;
            float v2 = sacc[nt][2] + bb1.x; if (mk0 != 0.f || w1.x <= 1e-5f) v2 = -INFINITY;
            float v3 = sacc[nt][3] + bb1.y; if (mk1 != 0.f || w1.y <= 1e-5f) v3 = -INFINITY;
            sacc[nt][0] = v0; sacc[nt][1] = v1; sacc[nt][2] = v2; sacc[nt][3] = v3;
            rmax0 = fmaxf(rmax0, fmaxf(v0, v1));
            rmax1 = fmaxf(rmax1, fmaxf(v2, v3));
        }
        rmax0 = fmaxf(rmax0, __shfl_xor_sync(0xffffffffu, rmax0, 1));
        rmax0 = fmaxf(rmax0, __shfl_xor_sync(0xffffffffu, rmax0, 2));
        rmax1 = fmaxf(rmax1, __shfl_xor_sync(0xffffffffu, rmax1, 1));
        rmax1 = fmaxf(rmax1, __shfl_xor_sync(0xffffffffu, rmax1, 2));

        float mn0 = fmaxf(m0, rmax0), mn1 = fmaxf(m1, rmax1);
        float sc0 = (mn0 == -INFINITY) ? 1.f : __expf(m0 - mn0);
        float sc1 = (mn1 == -INFINITY) ? 1.f : __expf(m1 - mn1);
        m0 = mn0; m1 = mn1;

        // ---- pass 2: exp, p = e*lw, pack bf16 hi/lo A-frags ----
        float ps0 = 0.f, ps1 = 0.f;
        uint32_t pah[8][2], pal[8][2];
#pragma unroll
        for (int nt = 0; nt < 8; nt++) {
            int col = kc + 8 * nt + 2 * tig;
            float2 w0 = __ldg((const float2*)(lwB + (size_t)(qw + gid)     * SSQ + col));
            float2 w1 = __ldg((const float2*)(lwB + (size_t)(qw + gid + 8) * SSQ + col));
            float e0 = (sacc[nt][0] == -INFINITY) ? 0.f : __expf(sacc[nt][0] - mn0);
            float e1 = (sacc[nt][1] == -INFINITY) ? 0.f : __expf(sacc[nt][1] - mn0);
            float e2 = (sacc[nt][2] == -INFINITY) ? 0.f : __expf(sacc[nt][2] - mn1);
            float e3 = (sacc[nt][3] == -INFINITY) ? 0.f : __expf(sacc[nt][3] - mn1);
            ps0 += e0 + e1; ps1 += e2 + e3;
            float p0 = e0 * w0.x, p1 = e1 * w0.y, p2 = e2 * w1.x, p3 = e3 * w1.y;
            __nv_bfloat16 h0, h1, h2, h3, lo0, lo1, lo2, lo3;
            bsplit(p0, h0, lo0); bsplit(p1, h1, lo1);
            bsplit(p2, h2, lo2); bsplit(p3, h3, lo3);
            __nv_bfloat162 t;
            t = __nv_bfloat162(h0, h1);  pah[nt][0] = *(uint32_t*)&t;
            t = __nv_bfloat162(h2, h3);  pah[nt][1] = *(uint32_t*)&t;
            t = __nv_bfloat162(lo0, lo1); pal[nt][0] = *(uint32_t*)&t;
            t = __nv_bfloat162(lo2, lo3); pal[nt][1] = *(uint32_t*)&t;
        }
        ps0 += __shfl_xor_sync(0xffffffffu, ps0, 1);
        ps0 += __shfl_xor_sync(0xffffffffu, ps0, 2);
        ps1 += __shfl_xor_sync(0xffffffffu, ps1, 1);
        ps1 += __shfl_xor_sync(0xffffffffu, ps1, 2);
        l0 = l0 * sc0 + ps0;
        l1 = l1 * sc1 + ps1;

#pragma unroll
        for (int nt = 0; nt < 8; nt++) {
            pacc[nt][0] *= sc0; pacc[nt][1] *= sc0;
            pacc[nt][2] *= sc1; pacc[nt][3] *= sc1;
        }

        // ---- PV (3-pass bf16x2), P frags from registers ----
#pragma unroll
        for (int ks = 0; ks < 4; ks++) {
            uint32_t ah0 = pah[2*ks][0],   ah1 = pah[2*ks][1];
            uint32_t ah2 = pah[2*ks+1][0], ah3 = pah[2*ks+1][1];
            uint32_t al0 = pal[2*ks][0],   al1 = pal[2*ks][1];
            uint32_t al2 = pal[2*ks+1][0], al3 = pal[2*ks+1][1];
#pragma unroll
            for (int nt = 0; nt < 8; nt++) {
                int rr = (8 * nt + gid) * 72 + 2 * tig + 16 * ks;
                uint32_t vh0 = *(uint32_t*)&Vthi[rr];
                uint32_t vh1 = *(uint32_t*)&Vthi[rr + 8];
                uint32_t vl0 = *(uint32_t*)&Vtlo[rr];
                uint32_t vl1 = *(uint32_t*)&Vtlo[rr + 8];
                mma16816(pacc[nt], ah0, ah1, ah2, ah3, vh0, vh1);
                mma16816(pacc[nt], al0, al1, al2, al3, vh0, vh1);
                mma16816(pacc[nt], ah0, ah1, ah2, ah3, vl0, vl1);
            }
        }
    }

    // ---- epilogue ----
    float inv0 = 1.f / l0, inv1 = 1.f / l1;
#pragma unroll
    for (int nt = 0; nt < 8; nt++) {
        int d = 8 * nt + 2 * tig;
        size_t o0 = (size_t)(b * TT + q0 + qw + gid)     * HHC + h * HDD + d;
        size_t o1 = (size_t)(b * TT + q0 + qw + gid + 8) * HHC + h * HDD + d;
        *(float2*)(g_att + o0) = make_float2(pacc[nt][0] * inv0, pacc[nt][1] * inv0);
        *(float2*)(g_att + o1) = make_float2(pacc[nt][2] * inv1, pacc[nt][3] * inv1);
    }
}

// ---------------- LayerNorm over H=1024 ----------------
__global__ __launch_bounds__(256) void ln_kernel(
    const float* __restrict__ gam, const float* __restrict__ bet)
{
    __shared__ float red[2][32];
    int row = blockIdx.x;
    const float* x = g_att + (size_t)row * HHC;
    float v[4], s = 0.f, sq = 0.f;
#pragma unroll
    for (int i = 0; i < 4; i++) {
        v[i] = x[threadIdx.x + i * 256];
        s += v[i]; sq += v[i] * v[i];
    }
#pragma unroll
    for (int o = 16; o; o >>= 1) {
        s  += __shfl_xor_sync(0xffffffffu, s,  o);
        sq += __shfl_xor_sync(0xffffffffu, sq, o);
    }
    int lane = threadIdx.x & 31, w = threadIdx.x >> 5;
    if (lane == 0) { red[0][w] = s; red[1][w] = sq; }
    __syncthreads();
    if (w == 0) {
        s  = (lane < 8) ? red[0][lane] : 0.f;
        sq = (lane < 8) ? red[1][lane] : 0.f;
#pragma unroll
        for (int o = 4; o; o >>= 1) {
            s  += __shfl_xor_sync(0xffffffffu, s,  o);
            sq += __shfl_xor_sync(0xffffffffu, sq, o);
        }
        if (lane == 0) { red[0][0] = s; red[1][0] = sq; }
    }
    __syncthreads();
    float mu  = red[0][0] * (1.f / HHC);
    float var = red[1][0] * (1.f / HHC) - mu * mu;
    float rs  = rsqrtf(var + LN_EPS);
#pragma unroll
    for (int i = 0; i < 4; i++) {
        int c = threadIdx.x + i * 256;
        g_ln[(size_t)row * HHC + c] = (v[i] - mu) * rs * gam[c] + bet[c];
    }
}

// ---------------- launch ----------------
extern "C" void kernel_launch(void* const* d_in, const int* in_sizes, int n_in,
                              void* d_out, int out_size)
{
    const float* x    = (const float*)d_in[0];
    const float* bias = (const float*)d_in[1];
    const float* lw   = (const float*)d_in[2];
    const unsigned char* kpm = (const unsigned char*)d_in[3];
    const int*   outcell = (const int*)d_in[4];
    const unsigned char* epm = (const unsigned char*)d_in[5];
    const float* wq  = (const float*)d_in[6];
    const float* wk  = (const float*)d_in[7];
    const float* wv  = (const float*)d_in[8];
    const float* wo  = (const float*)d_in[9];
    const float* lng = (const float*)d_in[10];
    const float* lnb = (const float*)d_in[11];
    float* out = (float*)d_out;

    float *Q, *K, *V, *LN;
    cudaGetSymbolAddress((void**)&Q,  g_Q);
    cudaGetSymbolAddress((void**)&K,  g_K);
    cudaGetSymbolAddress((void**)&V,  g_V);
    cudaGetSymbolAddress((void**)&LN, g_ln);

    dim3 gg(HHC / 128, (BB * TT) / 128);
    gemm_tf32_nt<<<gg, 256>>>(x, wq, Q, BB * TT, HHC, HHC, SCALING);
    gemm_tf32_nt<<<gg, 256>>>(x, wk, K, BB * TT, HHC, HHC, 1.f);
    gemm_tf32_nt<<<gg, 256>>>(x, wv, V, BB * TT, HHC, HHC, 1.f);

    rope_q_kernel<<<(BB * TT * NHH * 32) / 256, 256>>>();
    gather_kv_kernel<<<(BB * SSQ * NHH * 32) / 256, 256>>>(outcell);

    attn_mma_kernel<<<dim3(TT / 128, NHH, BB), 256, ATT_SMEM>>>(bias, lw, kpm, epm);

    ln_kernel<<<BB * TT, 256>>>(lng, lnb);

    gemm_tf32_nt<<<gg, 256>>>(LN, wo, out, BB * TT, HHC, HHC, 1.f);
}